// round 7
// baseline (speedup 1.0000x reference)
#include <cuda_runtime.h>

// Potential_6347961663538 — Gaussian form-factor splatting onto a 128x128 grid.
//
// out[b,i,j] = sum_a sum_f (ff_a*4π/ff_b)[a,f] *
//              exp(-π*(4π/ff_b)[a,f] * ((j-64-c0[b,a])^2 + (i-64-c1[b,a])^2))
//
// π·invb = 4π²/ff_b >= 19.74, so any term with per-axis |d| > 3.5 underflows
// fp32 exp to exactly 0 — identical to the zeros the reference adds. A 7x7
// window around round(coord) reproduces every nonzero fp32 term.
//
// R7: single-node tiled GATHER (two-node memset+scatter graph had ~3.4us of
// fixed node overhead + serial dependency). 128 blocks = (batch, band); band
// owns rows {band+32k, k=0..3} (strided -> uniform load by construction:
// an atom's 7-row window covers 7 consecutive residues mod 32, so it lands
// in <=7 blocks with exactly ONE row each, ~448 entries/block everywhere).
// Block pipeline: scan atoms -> smem queue -> bulk ff-constant load ->
// compute (4 entries x 7 px per warp-call, 5 ex2/lane) with smem atomics
// into a 4x128 band image -> plain coalesced STG. Output fully overwritten:
// no memset node, no global atomics, one kernel node.

#define SIDELEN 128
#define NATOM   2048
#define NB      4
#define NF      5
#define RAD     3
#define WIN     7
#define NBAND   32
#define THREADS 512
#define NWARP   (THREADS / 32)
#define CAP     2048          // each atom pushes <=1 entry per block

// dynamic smem layout (bytes):
//   img   :  512 floats              (4 rows x 128)
//   cxy   :  CAP float2              (atom coords)
//   pc    :  CAP*5 float2            ((p2, coef) per (entry, f))
//   meta  :  CAP int                 (row<<16 | atom)
#define SMEM_BYTES (512*4 + CAP*8 + CAP*5*8 + CAP*4)

__device__ __forceinline__ float ex2_approx(float x) {
    float r;
    asm("ex2.approx.f32 %0, %1;" : "=f"(r) : "f"(x));
    return r;
}

__global__ void __launch_bounds__(THREADS) potential_gather_kernel(
    const float* __restrict__ coords,   // [NB, NATOM, 3]
    const float* __restrict__ ff_a,     // [NATOM, NF]
    const float* __restrict__ ff_b,     // [NATOM, NF]
    float* __restrict__ out)            // [NB, SIDELEN, SIDELEN]
{
    extern __shared__ float smem[];
    float*  s_img  = smem;                               // [512]
    float2* s_cxy  = (float2*)(smem + 512);              // [CAP]
    float2* s_pc   = (float2*)(smem + 512 + CAP * 2);    // [CAP*5]
    int*    s_meta = (int*)   (smem + 512 + CAP * 12);   // [CAP]
    __shared__ int s_cnt;

    const int b    = blockIdx.x >> 5;
    const int band = blockIdx.x & (NBAND - 1);
    const int t    = threadIdx.x;

    // ---- init ----
    s_img[t] = 0.0f;
    if (t == 0) s_cnt = 0;
    __syncthreads();

    // ---- Phase A: scan this batch's atoms, queue (atom, row) hits ----
    const float* cb = coords + ((size_t)b << 11) * 3;
    #pragma unroll
    for (int k = 0; k < NATOM / THREADS; ++k) {
        const int a  = k * THREADS + t;
        const float c0 = cb[a * 3 + 0];
        const float c1 = cb[a * 3 + 1];
        const int jc = __float2int_rn(c0);
        const int ic = __float2int_rn(c1);
        // column prune: window cols jc+61 .. jc+67
        if (jc + 61 + 2 * RAD >= 0 && jc + 61 <= SIDELEN - 1) {
            const int lo = max(ic + 61, 0);
            const int hi = min(ic + 61 + 2 * RAD, SIDELEN - 1);
            if (lo <= hi) {
                const int r = lo + ((band - lo) & (NBAND - 1));
                if (r <= hi) {
                    const int pos = atomicAdd(&s_cnt, 1);
                    s_cxy[pos]  = make_float2(c0, c1);
                    s_meta[pos] = (r << 16) | a;
                }
            }
        }
    }
    __syncthreads();
    const int cnt = s_cnt;

    // ---- Phase B: bulk-load ff constants for queued entries ----
    for (int idx = t; idx < cnt * NF; idx += THREADS) {
        const int e = idx / NF;
        const int f = idx - e * NF;
        const int a = s_meta[e] & 0xffff;
        const float fb = ff_b[a * NF + f];
        const float fa = ff_a[a * NF + f];
        const float inv = __fdividef(1.0f, fb);
        // p2 = -(4π²·log2e)/ff_b ; coef = ff_a·4π/ff_b
        s_pc[idx] = make_float2(-56.9553183f * inv, fa * 12.56637061f * inv);
    }
    __syncthreads();

    // ---- Phase C: 4 entries per warp-call, 7 pixels per entry ----
    const int warp = t >> 5;
    const int lane = t & 31;
    const int sub  = lane >> 3;          // entry slot 0..3
    const int px   = lane & 7;           // window col 0..6 (7 idle lanes: px==7)
    const int nrounds = (cnt + NWARP * 4 - 1) / (NWARP * 4);

    for (int rd = 0; rd < nrounds; ++rd) {
        const int e = (rd * NWARP + warp) * 4 + sub;
        if (e < cnt && px < WIN) {
            const float2 c  = s_cxy[e];
            const int meta  = s_meta[e];
            const int r     = meta >> 16;
            const int jc    = __float2int_rn(c.x);
            const int j     = jc + 61 + px;
            const float dx  = (float)(jc - RAD + px) - c.x;
            const float dy  = (float)(r - SIDELEN / 2) - c.y;
            const float dd  = fmaf(dx, dx, dy * dy);
            const float2* pce = &s_pc[e * NF];
            const float2 q0 = pce[0], q1 = pce[1], q2 = pce[2],
                         q3 = pce[3], q4 = pce[4];
            float s =           q0.y * ex2_approx(q0.x * dd);
            s = fmaf(q1.y, ex2_approx(q1.x * dd), s);
            s = fmaf(q2.y, ex2_approx(q2.x * dd), s);
            s = fmaf(q3.y, ex2_approx(q3.x * dd), s);
            s = fmaf(q4.y, ex2_approx(q4.x * dd), s);
            if ((unsigned)j < SIDELEN && s != 0.0f)
                atomicAdd(&s_img[((r >> 5) << 7) + j], s);
        }
    }
    __syncthreads();

    // ---- Phase D: write the 4 owned rows (plain stores, no zero-init) ----
    {
        const int k   = t >> 7;                  // 0..3
        const int col = t & (SIDELEN - 1);
        const int row = band + (k << 5);
        out[(b << 14) + (row << 7) + col] = s_img[t];
    }
}

extern "C" void kernel_launch(void* const* d_in, const int* in_sizes, int n_in,
                              void* d_out, int out_size) {
    const float* coords = (const float*)d_in[0];
    const float* ff_a   = (const float*)d_in[1];
    const float* ff_b   = (const float*)d_in[2];
    float* out = (float*)d_out;

    static int configured = 0;
    if (!configured) {
        cudaFuncSetAttribute(potential_gather_kernel,
                             cudaFuncAttributeMaxDynamicSharedMemorySize,
                             SMEM_BYTES);
        configured = 1;
    }

    potential_gather_kernel<<<NB * NBAND, THREADS, SMEM_BYTES>>>(
        coords, ff_a, ff_b, out);
}

// round 8
// speedup vs baseline: 1.0652x; 1.0652x over previous
#include <cuda_runtime.h>

// Potential_6347961663538 — Gaussian form-factor splatting onto a 128x128 grid.
//
// out[b,i,j] = sum_a sum_f (ff_a·4π/ff_b)[a,f] *
//              exp(-π·(4π/ff_b)[a,f] · ((j-64-c0[b,a])² + (i-64-c1[b,a])²))
//
// π·invb = 4π²/ff_b >= 19.74, so any term with per-axis |d| > 3.5 underflows
// fp32 exp to exactly 0 — identical to the zeros the reference adds. A 7x7
// window around round(coord) reproduces every nonzero fp32 term.
//
// R8: SINGLE graph node. R7 measured the two-node graph's fixed overhead at
// ~3.4us (single-node gap is 0.13us), so the memset node is fused in: each
// block zeroes its exclusive 64-float slice of out, then a resident-grid
// software barrier (monotonic device counter; launches are serialized so
// every block derives the same per-launch target) orders all zeroing before
// any atomic. Grid is single-wave by construction: __launch_bounds__(256,8)
// caps regs at 32 -> 8 blocks/SM x 148 SMs = 1184 >= 1024 blocks, so the
// spin cannot deadlock. All per-atom compute (ff loads, RCP, shuffles, EX2)
// runs between barrier-arrive and barrier-wait, hiding the wait entirely;
// only the 2 REDs per lane run after release.

#define SIDELEN 128
#define NATOM   2048
#define NB      4
#define NF      5
#define RAD     3
#define WIN     7
#define WPB     8
#define GRID    ((NB * NATOM) / WPB)    // 1024 blocks, single wave

__device__ unsigned g_bar = 0;          // monotonic arrival counter

__device__ __forceinline__ float ex2_approx(float x) {
    float r;
    asm("ex2.approx.f32 %0, %1;" : "=f"(r) : "f"(x));
    return r;
}

__device__ __forceinline__ unsigned ld_acquire(const unsigned* p) {
    unsigned v;
    asm volatile("ld.acquire.gpu.u32 %0, [%1];" : "=r"(v) : "l"(p) : "memory");
    return v;
}

__global__ void __launch_bounds__(WPB * 32, 8) potential_fused_kernel(
    const float* __restrict__ coords,   // [NB, NATOM, 3]
    const float* __restrict__ ff_a,     // [NATOM, NF]
    const float* __restrict__ ff_b,     // [NATOM, NF]
    float* __restrict__ out)            // [NB, SIDELEN, SIDELEN]
{
    const int t    = threadIdx.x;
    const int warp = blockIdx.x * WPB + (t >> 5);   // = b*NATOM + a
    const int lane = t & 31;
    const int a    = warp & (NATOM - 1);

    // ---- issue input loads immediately (latency overlaps everything) ----
    float fbv = 1.0f, fav = 0.0f;
    if (lane < NF) {
        fbv = __ldg(&ff_b[a * NF + lane]);
        fav = __ldg(&ff_a[a * NF + lane]);
    }
    const float c0 = __ldg(&coords[warp * 3 + 0]);  // maps to j (fast axis)
    const float c1 = __ldg(&coords[warp * 3 + 1]);  // maps to i (slow axis)

    // ---- zero this block's exclusive 64-float slice of out ----
    if (t < 16)
        *(float4*)&out[(blockIdx.x << 6) + (t << 2)] =
            make_float4(0.f, 0.f, 0.f, 0.f);
    __syncthreads();                     // slice-zero complete block-wide

    // ---- barrier arrive (thread 0) ----
    unsigned target = 0;
    if (t == 0) {
        __threadfence();                 // make zero stores visible device-wide
        const unsigned old = atomicAdd(&g_bar, 1u);
        target = old - (old % GRID) + GRID;   // same value in every block
    }

    // ---- per-atom compute, fully overlapped with other blocks' arrivals ----
    float p2 = 0.0f, cf = 0.0f;
    if (lane < NF) {
        const float inv = __fdividef(1.0f, fbv);
        p2 = -56.9553183f * inv;         // -(4π²·log2e)/ff_b
        cf = fav * 12.56637061f * inv;   // ff_a·4π/ff_b
    }
    const float p20 = __shfl_sync(0xffffffffu, p2, 0);
    const float p21 = __shfl_sync(0xffffffffu, p2, 1);
    const float p22 = __shfl_sync(0xffffffffu, p2, 2);
    const float p23 = __shfl_sync(0xffffffffu, p2, 3);
    const float p24 = __shfl_sync(0xffffffffu, p2, 4);
    const float cf0 = __shfl_sync(0xffffffffu, cf, 0);
    const float cf1 = __shfl_sync(0xffffffffu, cf, 1);
    const float cf2 = __shfl_sync(0xffffffffu, cf, 2);
    const float cf3 = __shfl_sync(0xffffffffu, cf, 3);
    const float cf4 = __shfl_sync(0xffffffffu, cf, 4);

    const int jc = __float2int_rn(c0);
    const int ic = __float2int_rn(c1);
    const float fx = (float)(jc - RAD) - c0;
    const float fy = (float)(ic - RAD) - c1;
    const int jb = jc + SIDELEN / 2 - RAD;
    const int ib = ic + SIDELEN / 2 - RAD;

    const int wi0 = lane / WIN, wj0 = lane - wi0 * WIN;
    const int pp  = lane + 32;
    const int wi1 = pp / WIN,   wj1 = pp - wi1 * WIN;

    float s0, s1;
    {
        const float dx = fx + (float)wj0, dy = fy + (float)wi0;
        const float dd = fmaf(dx, dx, dy * dy);
        float s =            cf0 * ex2_approx(p20 * dd);
        s = fmaf(cf1, ex2_approx(p21 * dd), s);
        s = fmaf(cf2, ex2_approx(p22 * dd), s);
        s = fmaf(cf3, ex2_approx(p23 * dd), s);
        s0 = fmaf(cf4, ex2_approx(p24 * dd), s);
    }
    {
        const float dx = fx + (float)wj1, dy = fy + (float)wi1;
        const float dd = fmaf(dx, dx, dy * dy);
        float s =            cf0 * ex2_approx(p20 * dd);
        s = fmaf(cf1, ex2_approx(p21 * dd), s);
        s = fmaf(cf2, ex2_approx(p22 * dd), s);
        s = fmaf(cf3, ex2_approx(p23 * dd), s);
        s1 = fmaf(cf4, ex2_approx(p24 * dd), s);
    }

    // ---- barrier wait + block release ----
    if (t == 0) {
        while (ld_acquire(&g_bar) < target)
            __nanosleep(32);
    }
    __syncthreads();                     // all zeroing device-wide is visible

    // ---- scatter (REDG; pipelined at L2 even same-address) ----
    float* outb = out + ((warp >> 11) << 14);
    {
        const int i = ib + wi0, j = jb + wj0;
        if ((unsigned)i < SIDELEN && (unsigned)j < SIDELEN && s0 != 0.0f)
            atomicAdd(&outb[(i << 7) + j], s0);
    }
    if (pp < WIN * WIN) {
        const int i = ib + wi1, j = jb + wj1;
        if ((unsigned)i < SIDELEN && (unsigned)j < SIDELEN && s1 != 0.0f)
            atomicAdd(&outb[(i << 7) + j], s1);
    }
}

extern "C" void kernel_launch(void* const* d_in, const int* in_sizes, int n_in,
                              void* d_out, int out_size) {
    const float* coords = (const float*)d_in[0];
    const float* ff_a   = (const float*)d_in[1];
    const float* ff_b   = (const float*)d_in[2];
    float* out = (float*)d_out;

    potential_fused_kernel<<<GRID, WPB * 32>>>(coords, ff_a, ff_b, out);
}